// round 1
// baseline (speedup 1.0000x reference)
#include <cuda_runtime.h>
#include <stdint.h>

// Problem constants (fixed shapes)
#define NB 2
#define NN 20000
#define NF 256
#define NE 640000
#define KDIM 512            // concat feature dim
#define MO 256              // output features
#define MTOT (NB*NN)        // 40000 GEMM rows

// ---------------- device scratch (no allocs allowed) ----------------
__device__ int   g_flag;                 // 1 if edge_index is int64
__device__ int   g_deg[NN];
__device__ int   g_off[NN + 1];
__device__ int   g_cursor[NN];
__device__ int   g_src[NE];
__device__ float g_agg[(size_t)NB * NN * NF];   // [B][N][F] mean-aggregated

// ---------------- helpers ----------------
__device__ __forceinline__ int load_idx(const void* ei, long long pos) {
    if (g_flag) return (int)((const long long*)ei)[pos];
    return ((const int*)ei)[pos];
}

__device__ __forceinline__ unsigned long long fma_f32x2(
    unsigned long long a, unsigned long long b, unsigned long long c) {
    unsigned long long d;
    asm("fma.rn.f32x2 %0, %1, %2, %3;" : "=l"(d) : "l"(a), "l"(b), "l"(c));
    return d;
}

__device__ __forceinline__ unsigned long long pack2(float a) {
    unsigned long long r;
    asm("mov.b64 %0, {%1, %1};" : "=l"(r) : "f"(a));
    return r;
}

// ---------------- kernels ----------------

// Detect int64 vs int32 edge_index. int64 non-negative values < 2^31 have the
// high 32-bit word == 0 for every element; int32 data interpreted as int2 pairs
// has .y = a real index, which is ~never 0 across 64 samples.
__global__ void detect_kernel(const void* ei) {
    if (threadIdx.x == 0) {
        const int2* p = (const int2*)ei;
        int is64 = 1;
        for (int i = 0; i < 64; i++) {
            if (p[i].y != 0) { is64 = 0; break; }
        }
        g_flag = is64;
    }
}

__global__ void zero_kernel() {
    int i = blockIdx.x * blockDim.x + threadIdx.x;
    if (i < NN) { g_deg[i] = 0; g_cursor[i] = 0; }
}

__global__ void count_kernel(const void* __restrict__ ei, int E) {
    int e = blockIdx.x * blockDim.x + threadIdx.x;
    if (e < E) {
        int t = load_idx(ei, (long long)E + e);
        atomicAdd(&g_deg[t], 1);
    }
}

// single-block exclusive scan of g_deg -> g_off (N=20000; 20 chunks of 1024)
__global__ void scan_kernel(int n) {
    __shared__ int sdata[1024];
    __shared__ int s_carry;
    int tid = threadIdx.x;
    if (tid == 0) s_carry = 0;
    __syncthreads();
    for (int base = 0; base < n; base += 1024) {
        int i = base + tid;
        int v = (i < n) ? g_deg[i] : 0;
        sdata[tid] = v;
        __syncthreads();
        for (int off = 1; off < 1024; off *= 2) {
            int t = (tid >= off) ? sdata[tid - off] : 0;
            __syncthreads();
            sdata[tid] += t;
            __syncthreads();
        }
        int incl = sdata[tid];
        if (i < n) g_off[i] = s_carry + (incl - v);
        __syncthreads();
        if (tid == 0) s_carry += sdata[1023];
        __syncthreads();
    }
    if (tid == 0) g_off[n] = s_carry;
}

__global__ void fill_kernel(const void* __restrict__ ei, int E) {
    int e = blockIdx.x * blockDim.x + threadIdx.x;
    if (e < E) {
        int t = load_idx(ei, (long long)E + e);
        int s = load_idx(ei, e);
        int pos = atomicAdd(&g_cursor[t], 1);
        g_src[g_off[t] + pos] = s;
    }
}

// Pull-mode mean aggregation: one CTA per node, thread = feature, both batches.
__global__ void agg_kernel(const float* __restrict__ x) {
    int node = blockIdx.x;
    int f = threadIdx.x;
    int s0 = g_off[node], s1 = g_off[node + 1];
    const float* __restrict__ x0 = x;
    const float* __restrict__ x1 = x + (size_t)NN * NF;
    float a0 = 0.f, a1 = 0.f;
    __shared__ int sSrc[256];
    for (int base = s0; base < s1; base += 256) {
        int cnt = min(256, s1 - base);
        if (f < cnt) sSrc[f] = g_src[base + f];
        __syncthreads();
        int i = 0;
        for (; i + 4 <= cnt; i += 4) {
            int sA = sSrc[i], sB = sSrc[i + 1], sC = sSrc[i + 2], sD = sSrc[i + 3];
            float v0 = x0[(size_t)sA * NF + f];
            float v1 = x0[(size_t)sB * NF + f];
            float v2 = x0[(size_t)sC * NF + f];
            float v3 = x0[(size_t)sD * NF + f];
            float w0 = x1[(size_t)sA * NF + f];
            float w1 = x1[(size_t)sB * NF + f];
            float w2 = x1[(size_t)sC * NF + f];
            float w3 = x1[(size_t)sD * NF + f];
            a0 += (v0 + v1) + (v2 + v3);
            a1 += (w0 + w1) + (w2 + w3);
        }
        for (; i < cnt; i++) {
            int s = sSrc[i];
            a0 += x0[(size_t)s * NF + f];
            a1 += x1[(size_t)s * NF + f];
        }
        __syncthreads();
    }
    float inv = 1.0f / fmaxf((float)(s1 - s0), 1.0f);
    g_agg[(size_t)node * NF + f] = a0 * inv;
    g_agg[(size_t)(NN + node) * NF + f] = a1 * inv;
}

// GEMM: out[m][o] = relu( sum_k A[m][k]*Wcat[o][k] + b_l[o] )
//   A[m][k] = k<256 ? g_agg[m*256+k] : x[m*256+(k-256)]
//   Wcat[o][k] = k<256 ? W_l[o][k] : W_r[o][k-256]
// 128x128x16 tile, 256 threads, 8x8 micro-tile with fma.rn.f32x2.
#define BM 128
#define BN 128
#define BK 16
#define TM 8
#define TN2 4   // TN=8 as 4 f32x2 pairs

__global__ __launch_bounds__(256, 2)
void gemm_kernel(const float* __restrict__ xg,
                 const float* __restrict__ Wl,
                 const float* __restrict__ Wr,
                 const float* __restrict__ bl,
                 float* __restrict__ out) {
    __shared__ float As[BK][BM + 4];
    __shared__ float Bs[BK][BN + 4];

    int bm = blockIdx.x * BM;
    int bn = blockIdx.y * BN;
    int tid = threadIdx.x;
    int tx = tid & 15;   // 0..15 -> output cols tx*8
    int ty = tid >> 4;   // 0..15 -> output rows ty*8

    unsigned long long acc[TM][TN2];
#pragma unroll
    for (int i = 0; i < TM; i++)
#pragma unroll
        for (int j = 0; j < TN2; j++) acc[i][j] = 0ULL;

    for (int k0 = 0; k0 < KDIM; k0 += BK) {
        // load A tile (128 rows x 16 k), transposed into As[k][m]
#pragma unroll
        for (int r = 0; r < 2; r++) {
            int id = tid + r * 256;     // 0..511 float4 slots
            int row = id >> 2;          // 0..127
            int c4 = id & 3;            // 0..3
            int m = bm + row; if (m >= MTOT) m = MTOT - 1;
            int k = k0 + c4 * 4;
            const float* p = (k < NF) ? (g_agg + (size_t)m * NF + k)
                                      : (xg + (size_t)m * NF + (k - NF));
            float4 v = *(const float4*)p;
            As[c4 * 4 + 0][row] = v.x;
            As[c4 * 4 + 1][row] = v.y;
            As[c4 * 4 + 2][row] = v.z;
            As[c4 * 4 + 3][row] = v.w;
        }
        // load B tile (128 outputs x 16 k), transposed into Bs[k][o]
#pragma unroll
        for (int r = 0; r < 2; r++) {
            int id = tid + r * 256;
            int row = id >> 2;
            int c4 = id & 3;
            int o = bn + row;
            int k = k0 + c4 * 4;
            const float* p = (k < NF) ? (Wl + (size_t)o * NF + k)
                                      : (Wr + (size_t)o * NF + (k - NF));
            float4 v = *(const float4*)p;
            Bs[c4 * 4 + 0][row] = v.x;
            Bs[c4 * 4 + 1][row] = v.y;
            Bs[c4 * 4 + 2][row] = v.z;
            Bs[c4 * 4 + 3][row] = v.w;
        }
        __syncthreads();

#pragma unroll
        for (int kk = 0; kk < BK; kk++) {
            float a[TM];
            unsigned long long bv[TN2];
#pragma unroll
            for (int i = 0; i < TM; i++) a[i] = As[kk][ty * TM + i];
#pragma unroll
            for (int j = 0; j < TN2; j++)
                bv[j] = *(const unsigned long long*)&Bs[kk][tx * 8 + 2 * j];
#pragma unroll
            for (int i = 0; i < TM; i++) {
                unsigned long long a2 = pack2(a[i]);
#pragma unroll
                for (int j = 0; j < TN2; j++)
                    acc[i][j] = fma_f32x2(a2, bv[j], acc[i][j]);
            }
        }
        __syncthreads();
    }

    // epilogue: bias + relu
#pragma unroll
    for (int i = 0; i < TM; i++) {
        int m = bm + ty * TM + i;
        if (m < MTOT) {
#pragma unroll
            for (int j = 0; j < TN2; j++) {
                unsigned long long v = acc[i][j];
                float lo = __uint_as_float((unsigned)(v & 0xffffffffULL));
                float hi = __uint_as_float((unsigned)(v >> 32));
                int o = bn + tx * 8 + 2 * j;
                float r0 = fmaxf(lo + bl[o], 0.f);
                float r1 = fmaxf(hi + bl[o + 1], 0.f);
                out[(size_t)m * MO + o]     = r0;
                out[(size_t)m * MO + o + 1] = r1;
            }
        }
    }
}

// ---------------- launch ----------------
extern "C" void kernel_launch(void* const* d_in, const int* in_sizes, int n_in,
                              void* d_out, int out_size) {
    const float* x  = (const float*)d_in[0];
    const void*  ei = d_in[1];
    const float* Wl = (const float*)d_in[2];
    const float* bl = (const float*)d_in[3];
    const float* Wr = (const float*)d_in[4];
    float* out = (float*)d_out;
    int E = in_sizes[1] / 2;

    detect_kernel<<<1, 32>>>(ei);
    zero_kernel<<<(NN + 255) / 256, 256>>>();
    count_kernel<<<(E + 255) / 256, 256>>>(ei, E);
    scan_kernel<<<1, 1024>>>(NN);
    fill_kernel<<<(E + 255) / 256, 256>>>(ei, E);
    agg_kernel<<<NN, 256>>>(x);
    dim3 ggrid((MTOT + BM - 1) / BM, MO / BN);
    gemm_kernel<<<ggrid, 256>>>(x, Wl, Wr, bl, out);
}

// round 3
// speedup vs baseline: 1.5766x; 1.5766x over previous
#include <cuda_runtime.h>
#include <cuda_fp16.h>
#include <stdint.h>

// Problem constants (fixed shapes)
#define NB 2
#define NN 20000
#define NF 256
#define NE 640000
#define KDIM 512
#define MO 256
#define MTOT (NB*NN)        // 40000 GEMM rows

// ---------------- device scratch ----------------
__device__ int   g_flag;
__device__ int   g_deg[NN];
__device__ int   g_off[NN + 1];
__device__ int   g_cursor[NN];
__device__ int   g_src[NE];
// A matrix [MTOT][512] fp16 hi/lo. cols 0..255 = agg, 256..511 = x
__device__ __align__(16) __half g_Ahi[(size_t)MTOT * KDIM];
__device__ __align__(16) __half g_Alo[(size_t)MTOT * KDIM];
// W concat [256][512] fp16 hi/lo: k<256 from W_l, else W_r
__device__ __align__(16) __half g_Whi[(size_t)MO * KDIM];
__device__ __align__(16) __half g_Wlo[(size_t)MO * KDIM];

// ---------------- PTX helpers (base sm_103-safe only) ----------------
__device__ __forceinline__ uint32_t smem_u32(const void* p) {
    return (uint32_t)__cvta_generic_to_shared(p);
}
#define CP_ASYNC16(s, g) \
    asm volatile("cp.async.cg.shared.global [%0], [%1], 16;" :: "r"(s), "l"(g))
#define CP_COMMIT() asm volatile("cp.async.commit_group;" ::: "memory")
#define CP_WAIT0()  asm volatile("cp.async.wait_group 0;" ::: "memory")

__device__ __forceinline__ void ldmx4(uint32_t& r0, uint32_t& r1, uint32_t& r2, uint32_t& r3,
                                      uint32_t addr) {
    asm volatile("ldmatrix.sync.aligned.m8n8.x4.shared.b16 {%0,%1,%2,%3}, [%4];"
                 : "=r"(r0), "=r"(r1), "=r"(r2), "=r"(r3) : "r"(addr));
}
__device__ __forceinline__ void mma16816(float* c, const uint32_t* a, const uint32_t* b) {
    asm volatile(
        "mma.sync.aligned.m16n8k16.row.col.f32.f16.f16.f32 "
        "{%0,%1,%2,%3}, {%4,%5,%6,%7}, {%8,%9}, {%0,%1,%2,%3};"
        : "+f"(c[0]), "+f"(c[1]), "+f"(c[2]), "+f"(c[3])
        : "r"(a[0]), "r"(a[1]), "r"(a[2]), "r"(a[3]), "r"(b[0]), "r"(b[1]));
}

// ---------------- helpers ----------------
__device__ __forceinline__ int load_idx(const void* ei, long long pos) {
    if (g_flag) return (int)((const long long*)ei)[pos];
    return ((const int*)ei)[pos];
}

// ---------------- graph setup kernels ----------------
__global__ void detect_kernel(const void* ei) {
    if (threadIdx.x == 0) {
        const int2* p = (const int2*)ei;
        int is64 = 1;
        for (int i = 0; i < 64; i++)
            if (p[i].y != 0) { is64 = 0; break; }
        g_flag = is64;
    }
}

__global__ void zero_kernel() {
    int i = blockIdx.x * blockDim.x + threadIdx.x;
    if (i < NN) { g_deg[i] = 0; g_cursor[i] = 0; }
}

__global__ void count_kernel(const void* __restrict__ ei, int E) {
    int e = blockIdx.x * blockDim.x + threadIdx.x;
    if (e < E) atomicAdd(&g_deg[load_idx(ei, (long long)E + e)], 1);
}

// fast single-block scan: 1024 threads x 20 elems, shuffle scan
__global__ void scan_kernel() {
    __shared__ int warp_sums[32];
    const int CH = 20;   // 1024*20 = 20480 >= NN+1
    int t = threadIdx.x;
    int lane = t & 31, w = t >> 5;
    int base = t * CH;
    int v[CH];
    int s = 0;
#pragma unroll
    for (int i = 0; i < CH; i++) {
        int idx = base + i;
        int d = (idx < NN) ? g_deg[idx] : 0;
        s += d;
        v[i] = s;
    }
    int x = s;
#pragma unroll
    for (int off = 1; off < 32; off *= 2) {
        int y = __shfl_up_sync(0xffffffffu, x, off);
        if (lane >= off) x += y;
    }
    if (lane == 31) warp_sums[w] = x;
    __syncthreads();
    if (w == 0) {
        int ws = warp_sums[lane];
#pragma unroll
        for (int off = 1; off < 32; off *= 2) {
            int y = __shfl_up_sync(0xffffffffu, ws, off);
            if (lane >= off) ws += y;
        }
        warp_sums[lane] = ws;
    }
    __syncthreads();
    int thrExcl = ((w > 0) ? warp_sums[w - 1] : 0) + (x - s);
#pragma unroll
    for (int i = 0; i < CH; i++) {
        int idx = base + i;
        if (idx <= NN) g_off[idx] = thrExcl + (i == 0 ? 0 : v[i - 1]);
    }
}

__global__ void fill_kernel(const void* __restrict__ ei, int E) {
    int e = blockIdx.x * blockDim.x + threadIdx.x;
    if (e < E) {
        int t = load_idx(ei, (long long)E + e);
        int s = load_idx(ei, e);
        int pos = atomicAdd(&g_cursor[t], 1);
        g_src[g_off[t] + pos] = s;
    }
}

// ---------------- mean aggregation -> fp16 hi/lo A columns [0,256) ----------------
__global__ void agg_kernel(const float* __restrict__ x) {
    int node = blockIdx.x;
    int f = threadIdx.x;
    int s0 = g_off[node], s1 = g_off[node + 1];
    const float* __restrict__ x0 = x;
    const float* __restrict__ x1 = x + (size_t)NN * NF;
    float a0 = 0.f, a1 = 0.f;
    __shared__ int sSrc[256];
    for (int base = s0; base < s1; base += 256) {
        int cnt = min(256, s1 - base);
        if (f < cnt) sSrc[f] = g_src[base + f];
        __syncthreads();
        int i = 0;
        for (; i + 4 <= cnt; i += 4) {
            int sA = sSrc[i], sB = sSrc[i + 1], sC = sSrc[i + 2], sD = sSrc[i + 3];
            float v0 = x0[(size_t)sA * NF + f];
            float v1 = x0[(size_t)sB * NF + f];
            float v2 = x0[(size_t)sC * NF + f];
            float v3 = x0[(size_t)sD * NF + f];
            float w0 = x1[(size_t)sA * NF + f];
            float w1 = x1[(size_t)sB * NF + f];
            float w2 = x1[(size_t)sC * NF + f];
            float w3 = x1[(size_t)sD * NF + f];
            a0 += (v0 + v1) + (v2 + v3);
            a1 += (w0 + w1) + (w2 + w3);
        }
        for (; i < cnt; i++) {
            int s = sSrc[i];
            a0 += x0[(size_t)s * NF + f];
            a1 += x1[(size_t)s * NF + f];
        }
        __syncthreads();
    }
    float inv = 1.0f / fmaxf((float)(s1 - s0), 1.0f);
    a0 *= inv; a1 *= inv;
    __half h0 = __float2half_rn(a0);
    __half l0 = __float2half_rn(a0 - __half2float(h0));
    __half h1 = __float2half_rn(a1);
    __half l1 = __float2half_rn(a1 - __half2float(h1));
    size_t r0 = (size_t)node * KDIM + f;
    size_t r1 = (size_t)(NN + node) * KDIM + f;
    g_Ahi[r0] = h0; g_Alo[r0] = l0;
    g_Ahi[r1] = h1; g_Alo[r1] = l1;
}

// ---------------- x -> fp16 hi/lo A columns [256,512) ----------------
__global__ void xconv_kernel(const float* __restrict__ x) {
    int idx = blockIdx.x * blockDim.x + threadIdx.x;
    const int TOT = MTOT * (NF / 4);
    if (idx >= TOT) return;
    int m = idx >> 6;            // 64 float4 per row
    int fq = (idx & 63) * 4;
    float4 v = ((const float4*)x)[idx];
    float a[4] = {v.x, v.y, v.z, v.w};
    union { __half b[4]; uint64_t u; } hi, lo;
#pragma unroll
    for (int i = 0; i < 4; i++) {
        hi.b[i] = __float2half_rn(a[i]);
        lo.b[i] = __float2half_rn(a[i] - __half2float(hi.b[i]));
    }
    size_t o = (size_t)m * KDIM + 256 + fq;
    *(uint64_t*)&g_Ahi[o] = hi.u;
    *(uint64_t*)&g_Alo[o] = lo.u;
}

// ---------------- W concat -> fp16 hi/lo ----------------
__global__ void wconv_kernel(const float* __restrict__ Wl, const float* __restrict__ Wr) {
    int idx = blockIdx.x * blockDim.x + threadIdx.x;
    if (idx >= MO * KDIM) return;
    int o = idx >> 9, k = idx & 511;
    float v = (k < NF) ? Wl[o * NF + k] : Wr[o * NF + (k - NF)];
    __half h = __float2half_rn(v);
    g_Whi[idx] = h;
    g_Wlo[idx] = __float2half_rn(v - __half2float(h));
}

// ---------------- mma.sync GEMM ----------------
// out[m][o] = relu( sum over 3 segments of Aseg[m][k]*Wseg[o][k] + b[o] )
// segments: (Ahi,Whi), (Ahi,Wlo), (Alo,Whi); virtual K = 1536, BK=32 -> 48 iters.
#define BM 128
#define BN 128
#define BK 32
#define NIT 48
#define SKW 40   // halves per smem row (32 + 8 pad): 80B stride, conflict-free ldmatrix

__global__ __launch_bounds__(256, 2)
void mma_gemm_kernel(const float* __restrict__ bl, float* __restrict__ out) {
    __shared__ __align__(16) __half As[2][BM * SKW];
    __shared__ __align__(16) __half Bs[2][BN * SKW];
    __shared__ float s_bias[BN];

    int tid = threadIdx.x;
    int lane = tid & 31, wid = tid >> 5;
    int bm = blockIdx.x * BM;
    int bn = blockIdx.y * BN;
    int wm = (wid & 3) * 32;     // warp tile 32x64
    int wn = (wid >> 2) * 64;

    if (tid < BN) s_bias[tid] = bl[bn + tid];

    uint32_t sA[2] = { smem_u32(&As[0][0]), smem_u32(&As[1][0]) };
    uint32_t sB[2] = { smem_u32(&Bs[0][0]), smem_u32(&Bs[1][0]) };

    float acc[2][8][4];
#pragma unroll
    for (int i = 0; i < 2; i++)
#pragma unroll
        for (int j = 0; j < 8; j++)
#pragma unroll
            for (int q = 0; q < 4; q++) acc[i][j][q] = 0.f;

    // tile loader: iteration it -> (segment, k0)
    auto load_tiles = [&](int it, int buf) {
        int seg = it >> 4;               // 16 iters per 512-K segment
        int k0 = (it & 15) << 5;
        const __half* __restrict__ Ap = (seg == 2) ? g_Alo : g_Ahi;
        const __half* __restrict__ Bp = (seg == 1) ? g_Wlo : g_Whi;
#pragma unroll
        for (int i = 0; i < 2; i++) {
            int c = tid + i * 256;       // 512 16B-chunks per tile
            int row = c >> 2, q = c & 3;
            int m = bm + row; if (m >= MTOT) m = MTOT - 1;
            CP_ASYNC16(sA[buf] + (row * SKW + q * 8) * 2,
                       Ap + (size_t)m * KDIM + k0 + q * 8);
            int n = bn + row;
            CP_ASYNC16(sB[buf] + (row * SKW + q * 8) * 2,
                       Bp + (size_t)n * KDIM + k0 + q * 8);
        }
        CP_COMMIT();
    };

    load_tiles(0, 0);
    int buf = 0;

    for (int it = 0; it < NIT; it++) {
        CP_WAIT0();
        __syncthreads();
        if (it + 1 < NIT) load_tiles(it + 1, buf ^ 1);

#pragma unroll
        for (int kk = 0; kk < 2; kk++) {
            uint32_t a[2][4], b[8][2];
#pragma unroll
            for (int mt = 0; mt < 2; mt++) {
                uint32_t addr = sA[buf] +
                    ((wm + mt * 16 + (lane & 15)) * SKW + kk * 16 + (lane >> 4) * 8) * 2;
                ldmx4(a[mt][0], a[mt][1], a[mt][2], a[mt][3], addr);
            }
#pragma unroll
            for (int np = 0; np < 4; np++) {
                int rowB = wn + np * 16 + (lane & 7) + ((lane >> 4) << 3);
                uint32_t addr = sB[buf] +
                    (rowB * SKW + kk * 16 + ((lane >> 3) & 1) * 8) * 2;
                ldmx4(b[2 * np][0], b[2 * np][1], b[2 * np + 1][0], b[2 * np + 1][1], addr);
            }
#pragma unroll
            for (int mt = 0; mt < 2; mt++)
#pragma unroll
                for (int nt = 0; nt < 8; nt++)
                    mma16816(acc[mt][nt], a[mt], b[nt]);
        }
        __syncthreads();
        buf ^= 1;
    }

    // epilogue: bias + relu, float2 stores
    int g = lane >> 2, t4 = lane & 3;
#pragma unroll
    for (int mt = 0; mt < 2; mt++) {
#pragma unroll
        for (int nt = 0; nt < 8; nt++) {
            int o = bn + wn + nt * 8 + t4 * 2;
            float b0 = s_bias[wn + nt * 8 + t4 * 2];
            float b1 = s_bias[wn + nt * 8 + t4 * 2 + 1];
            int m0 = bm + wm + mt * 16 + g;
            if (m0 < MTOT) {
                float2 v;
                v.x = fmaxf(acc[mt][nt][0] + b0, 0.f);
                v.y = fmaxf(acc[mt][nt][1] + b1, 0.f);
                *(float2*)(out + (size_t)m0 * MO + o) = v;
            }
            int m1 = m0 + 8;
            if (m1 < MTOT) {
                float2 v;
                v.x = fmaxf(acc[mt][nt][2] + b0, 0.f);
                v.y = fmaxf(acc[mt][nt][3] + b1, 0.f);
                *(float2*)(out + (size_t)m1 * MO + o) = v;
            }
        }
    }
}

// ---------------- launch ----------------
extern "C" void kernel_launch(void* const* d_in, const int* in_sizes, int n_in,
                              void* d_out, int out_size) {
    const float* x  = (const float*)d_in[0];
    const void*  ei = d_in[1];
    const float* Wl = (const float*)d_in[2];
    const float* bl = (const float*)d_in[3];
    const float* Wr = (const float*)d_in[4];
    float* out = (float*)d_out;
    int E = in_sizes[1] / 2;

    detect_kernel<<<1, 32>>>(ei);
    zero_kernel<<<(NN + 255) / 256, 256>>>();
    count_kernel<<<(E + 255) / 256, 256>>>(ei, E);
    scan_kernel<<<1, 1024>>>();
    fill_kernel<<<(E + 255) / 256, 256>>>(ei, E);
    agg_kernel<<<NN, 256>>>(x);
    xconv_kernel<<<(MTOT * (NF / 4) + 255) / 256, 256>>>(x);
    wconv_kernel<<<(MO * KDIM + 511) / 512, 512>>>(Wl, Wr);
    dim3 ggrid((MTOT + BM - 1) / BM, MO / BN);
    mma_gemm_kernel<<<ggrid, 256>>>(bl, out);
}

// round 4
// speedup vs baseline: 1.8245x; 1.1573x over previous
#include <cuda_runtime.h>
#include <cuda_fp16.h>
#include <stdint.h>

// Problem constants (fixed shapes)
#define NB 2
#define NN 20000
#define NF 256
#define NE 640000
#define KDIM 512
#define MO 256
#define MTOT (NB*NN)        // 40000 GEMM rows
#define NDEG_PAD 20480      // NN padded to int4 multiple for vector scan

// ---------------- device scratch ----------------
__device__ int   g_flag;
__device__ __align__(16) int g_deg[NDEG_PAD];
__device__ int   g_off[NN + 1];
__device__ int   g_cursor[NN];
__device__ int   g_src[NE];
// A matrix [MTOT][512] fp16 hi/lo. cols 0..255 = agg, 256..511 = x (fp16 copy of x)
__device__ __align__(16) __half g_Ahi[(size_t)MTOT * KDIM];
__device__ __align__(16) __half g_Alo[(size_t)MTOT * KDIM];
// W concat [256][512] fp16 hi/lo: k<256 from W_l, else W_r
__device__ __align__(16) __half g_Whi[(size_t)MO * KDIM];
__device__ __align__(16) __half g_Wlo[(size_t)MO * KDIM];

// ---------------- PTX helpers (base sm_103-safe only) ----------------
__device__ __forceinline__ uint32_t smem_u32(const void* p) {
    return (uint32_t)__cvta_generic_to_shared(p);
}
#define CP_ASYNC16(s, g) \
    asm volatile("cp.async.cg.shared.global [%0], [%1], 16;" :: "r"(s), "l"(g))
#define CP_COMMIT() asm volatile("cp.async.commit_group;" ::: "memory")
#define CP_WAIT0()  asm volatile("cp.async.wait_group 0;" ::: "memory")

__device__ __forceinline__ void ldmx4(uint32_t& r0, uint32_t& r1, uint32_t& r2, uint32_t& r3,
                                      uint32_t addr) {
    asm volatile("ldmatrix.sync.aligned.m8n8.x4.shared.b16 {%0,%1,%2,%3}, [%4];"
                 : "=r"(r0), "=r"(r1), "=r"(r2), "=r"(r3) : "r"(addr));
}
__device__ __forceinline__ void mma16816(float* c, const uint32_t* a, const uint32_t* b) {
    asm volatile(
        "mma.sync.aligned.m16n8k16.row.col.f32.f16.f16.f32 "
        "{%0,%1,%2,%3}, {%4,%5,%6,%7}, {%8,%9}, {%0,%1,%2,%3};"
        : "+f"(c[0]), "+f"(c[1]), "+f"(c[2]), "+f"(c[3])
        : "r"(a[0]), "r"(a[1]), "r"(a[2]), "r"(a[3]), "r"(b[0]), "r"(b[1]));
}

// ---------------- helpers ----------------
__device__ __forceinline__ int load_idx(const void* ei, long long pos) {
    if (g_flag) return (int)((const long long*)ei)[pos];
    return ((const int*)ei)[pos];
}

// ---------------- graph setup kernels ----------------
__global__ void detect_kernel(const void* ei) {
    if (threadIdx.x == 0) {
        const int2* p = (const int2*)ei;
        int is64 = 1;
        for (int i = 0; i < 64; i++)
            if (p[i].y != 0) { is64 = 0; break; }
        g_flag = is64;
    }
}

__global__ void zero_kernel() {
    int i = blockIdx.x * blockDim.x + threadIdx.x;
    if (i < NDEG_PAD) g_deg[i] = 0;
    if (i < NN) g_cursor[i] = 0;
}

__global__ void count_kernel(const void* __restrict__ ei, int E) {
    int e = blockIdx.x * blockDim.x + threadIdx.x;
    if (e < E) atomicAdd(&g_deg[load_idx(ei, (long long)E + e)], 1);
}

// single-block scan: 1024 threads x 20 elems (5 int4), shuffle scan
__global__ void scan_kernel() {
    __shared__ int warp_sums[32];
    const int CH = 20;
    int t = threadIdx.x;
    int lane = t & 31, w = t >> 5;
    int v[CH];
    {
        int4 wv[5];
#pragma unroll
        for (int q = 0; q < 5; q++) wv[q] = ((const int4*)g_deg)[t * 5 + q];
        int s = 0;
#pragma unroll
        for (int q = 0; q < 5; q++) {
            s += wv[q].x; v[q * 4 + 0] = s;
            s += wv[q].y; v[q * 4 + 1] = s;
            s += wv[q].z; v[q * 4 + 2] = s;
            s += wv[q].w; v[q * 4 + 3] = s;
        }
    }
    int s = v[CH - 1];
    int x = s;
#pragma unroll
    for (int off = 1; off < 32; off *= 2) {
        int y = __shfl_up_sync(0xffffffffu, x, off);
        if (lane >= off) x += y;
    }
    if (lane == 31) warp_sums[w] = x;
    __syncthreads();
    if (w == 0) {
        int ws = warp_sums[lane];
#pragma unroll
        for (int off = 1; off < 32; off *= 2) {
            int y = __shfl_up_sync(0xffffffffu, ws, off);
            if (lane >= off) ws += y;
        }
        warp_sums[lane] = ws;
    }
    __syncthreads();
    int thrExcl = ((w > 0) ? warp_sums[w - 1] : 0) + (x - s);
    int base = t * CH;
#pragma unroll
    for (int i = 0; i < CH; i++) {
        int idx = base + i;
        if (idx <= NN) g_off[idx] = thrExcl + (i == 0 ? 0 : v[i - 1]);
    }
}

__global__ void fill_kernel(const void* __restrict__ ei, int E) {
    int e = blockIdx.x * blockDim.x + threadIdx.x;
    if (e < E) {
        int t = load_idx(ei, (long long)E + e);
        int s = load_idx(ei, e);
        int pos = atomicAdd(&g_cursor[t], 1);
        g_src[g_off[t] + pos] = s;
    }
}

// ---------------- x -> fp16 hi/lo A columns [256,512) ----------------
__global__ void xconv_kernel(const float* __restrict__ x) {
    int idx = blockIdx.x * blockDim.x + threadIdx.x;
    const int TOT = MTOT * (NF / 4);
    if (idx >= TOT) return;
    int m = idx >> 6;            // 64 float4 per row
    int fq = (idx & 63) * 4;
    float4 v = ((const float4*)x)[idx];
    float a[4] = {v.x, v.y, v.z, v.w};
    union { __half b[4]; uint64_t u; } hi, lo;
#pragma unroll
    for (int i = 0; i < 4; i++) {
        hi.b[i] = __float2half_rn(a[i]);
        lo.b[i] = __float2half_rn(a[i] - __half2float(hi.b[i]));
    }
    size_t o = (size_t)m * KDIM + 256 + fq;
    *(uint64_t*)&g_Ahi[o] = hi.u;
    *(uint64_t*)&g_Alo[o] = lo.u;
}

// ---------------- mean aggregation: fp16 gather from g_Ahi x-columns ----------------
// 64 threads per node: threads 0-31 batch 0, 32-63 batch 1; thread covers 8 features.
__device__ __forceinline__ void acc8(float* acc, uint4 v) {
    const __half2* h = (const __half2*)&v;
#pragma unroll
    for (int q = 0; q < 4; q++) {
        float2 f = __half22float2(h[q]);
        acc[2 * q]     += f.x;
        acc[2 * q + 1] += f.y;
    }
}

__global__ __launch_bounds__(64)
void agg_kernel() {
    int node = blockIdx.x;
    int t = threadIdx.x;
    int batch = t >> 5, lane = t & 31;
    int s0 = g_off[node], s1 = g_off[node + 1];
    __shared__ int sSrc[64];
    const uint4* __restrict__ xb = (const uint4*)g_Ahi;  // 64 uint4 per row
    size_t bbase = (size_t)batch * NN;
    float acc[8] = {0.f, 0.f, 0.f, 0.f, 0.f, 0.f, 0.f, 0.f};

    for (int base = s0; base < s1; base += 64) {
        int cnt = min(64, s1 - base);
        if (t < cnt) sSrc[t] = g_src[base + t];
        __syncthreads();
        int i = 0;
        for (; i + 4 <= cnt; i += 4) {
            uint4 v0 = xb[(bbase + sSrc[i + 0]) * 64 + 32 + lane];
            uint4 v1 = xb[(bbase + sSrc[i + 1]) * 64 + 32 + lane];
            uint4 v2 = xb[(bbase + sSrc[i + 2]) * 64 + 32 + lane];
            uint4 v3 = xb[(bbase + sSrc[i + 3]) * 64 + 32 + lane];
            acc8(acc, v0); acc8(acc, v1); acc8(acc, v2); acc8(acc, v3);
        }
        for (; i < cnt; i++) {
            uint4 v = xb[(bbase + sSrc[i]) * 64 + 32 + lane];
            acc8(acc, v);
        }
        __syncthreads();
    }

    float inv = 1.0f / fmaxf((float)(s1 - s0), 1.0f);
    union { __half h[8]; uint4 u; } hi, lo;
#pragma unroll
    for (int j = 0; j < 8; j++) {
        float a = acc[j] * inv;
        hi.h[j] = __float2half_rn(a);
        lo.h[j] = __float2half_rn(a - __half2float(hi.h[j]));
    }
    size_t off = (bbase + node) * (size_t)KDIM + lane * 8;
    *(uint4*)&g_Ahi[off] = hi.u;
    *(uint4*)&g_Alo[off] = lo.u;
}

// ---------------- W concat -> fp16 hi/lo ----------------
__global__ void wconv_kernel(const float* __restrict__ Wl, const float* __restrict__ Wr) {
    int idx = blockIdx.x * blockDim.x + threadIdx.x;
    if (idx >= MO * KDIM) return;
    int o = idx >> 9, k = idx & 511;
    float v = (k < NF) ? Wl[o * NF + k] : Wr[o * NF + (k - NF)];
    __half h = __float2half_rn(v);
    g_Whi[idx] = h;
    g_Wlo[idx] = __float2half_rn(v - __half2float(h));
}

// ---------------- mma.sync GEMM ----------------
// out[m][o] = relu( sum over 3 segments of Aseg[m][k]*Wseg[o][k] + b[o] )
// segments: (Ahi,Whi), (Ahi,Wlo), (Alo,Whi); virtual K = 1536, BK=32 -> 48 iters.
#define BM 128
#define BN 128
#define BK 32
#define NIT 48
#define SKW 40   // halves per smem row (32 + 8 pad)

__global__ __launch_bounds__(256, 2)
void mma_gemm_kernel(const float* __restrict__ bl, float* __restrict__ out) {
    __shared__ __align__(16) __half As[2][BM * SKW];
    __shared__ __align__(16) __half Bs[2][BN * SKW];
    __shared__ float s_bias[BN];

    int tid = threadIdx.x;
    int lane = tid & 31, wid = tid >> 5;
    int bm = blockIdx.x * BM;
    int bn = blockIdx.y * BN;
    int wm = (wid & 3) * 32;     // warp tile 32x64
    int wn = (wid >> 2) * 64;

    if (tid < BN) s_bias[tid] = bl[bn + tid];

    uint32_t sA[2] = { smem_u32(&As[0][0]), smem_u32(&As[1][0]) };
    uint32_t sB[2] = { smem_u32(&Bs[0][0]), smem_u32(&Bs[1][0]) };

    float acc[2][8][4];
#pragma unroll
    for (int i = 0; i < 2; i++)
#pragma unroll
        for (int j = 0; j < 8; j++)
#pragma unroll
            for (int q = 0; q < 4; q++) acc[i][j][q] = 0.f;

    auto load_tiles = [&](int it, int buf) {
        int seg = it >> 4;               // 16 iters per 512-K segment
        int k0 = (it & 15) << 5;
        const __half* __restrict__ Ap = (seg == 2) ? g_Alo : g_Ahi;
        const __half* __restrict__ Bp = (seg == 1) ? g_Wlo : g_Whi;
#pragma unroll
        for (int i = 0; i < 2; i++) {
            int c = tid + i * 256;       // 512 16B-chunks per tile
            int row = c >> 2, q = c & 3;
            int m = bm + row; if (m >= MTOT) m = MTOT - 1;
            CP_ASYNC16(sA[buf] + (row * SKW + q * 8) * 2,
                       Ap + (size_t)m * KDIM + k0 + q * 8);
            int n = bn + row;
            CP_ASYNC16(sB[buf] + (row * SKW + q * 8) * 2,
                       Bp + (size_t)n * KDIM + k0 + q * 8);
        }
        CP_COMMIT();
    };

    load_tiles(0, 0);
    int buf = 0;

    for (int it = 0; it < NIT; it++) {
        CP_WAIT0();
        __syncthreads();
        if (it + 1 < NIT) load_tiles(it + 1, buf ^ 1);

#pragma unroll
        for (int kk = 0; kk < 2; kk++) {
            uint32_t a[2][4], b[8][2];
#pragma unroll
            for (int mt = 0; mt < 2; mt++) {
                uint32_t addr = sA[buf] +
                    ((wm + mt * 16 + (lane & 15)) * SKW + kk * 16 + (lane >> 4) * 8) * 2;
                ldmx4(a[mt][0], a[mt][1], a[mt][2], a[mt][3], addr);
            }
#pragma unroll
            for (int np = 0; np < 4; np++) {
                int rowB = wn + np * 16 + (lane & 7) + ((lane >> 4) << 3);
                uint32_t addr = sB[buf] +
                    (rowB * SKW + kk * 16 + ((lane >> 3) & 1) * 8) * 2;
                ldmx4(b[2 * np][0], b[2 * np][1], b[2 * np + 1][0], b[2 * np + 1][1], addr);
            }
#pragma unroll
            for (int mt = 0; mt < 2; mt++)
#pragma unroll
                for (int nt = 0; nt < 8; nt++)
                    mma16816(acc[mt][nt], a[mt], b[nt]);
        }
        __syncthreads();
        buf ^= 1;
    }

    // epilogue: bias + relu, float2 stores
    int g = lane >> 2, t4 = lane & 3;
#pragma unroll
    for (int mt = 0; mt < 2; mt++) {
#pragma unroll
        for (int nt = 0; nt < 8; nt++) {
            int o = bn + wn + nt * 8 + t4 * 2;
            float b0 = s_bias[wn + nt * 8 + t4 * 2];
            float b1 = s_bias[wn + nt * 8 + t4 * 2 + 1];
            int m0 = bm + wm + mt * 16 + g;
            if (m0 < MTOT) {
                float2 v;
                v.x = fmaxf(acc[mt][nt][0] + b0, 0.f);
                v.y = fmaxf(acc[mt][nt][1] + b1, 0.f);
                *(float2*)(out + (size_t)m0 * MO + o) = v;
            }
            int m1 = m0 + 8;
            if (m1 < MTOT) {
                float2 v;
                v.x = fmaxf(acc[mt][nt][2] + b0, 0.f);
                v.y = fmaxf(acc[mt][nt][3] + b1, 0.f);
                *(float2*)(out + (size_t)m1 * MO + o) = v;
            }
        }
    }
}

// ---------------- launch ----------------
extern "C" void kernel_launch(void* const* d_in, const int* in_sizes, int n_in,
                              void* d_out, int out_size) {
    const float* x  = (const float*)d_in[0];
    const void*  ei = d_in[1];
    const float* Wl = (const float*)d_in[2];
    const float* bl = (const float*)d_in[3];
    const float* Wr = (const float*)d_in[4];
    float* out = (float*)d_out;
    int E = in_sizes[1] / 2;

    detect_kernel<<<1, 32>>>(ei);
    zero_kernel<<<(NDEG_PAD + 255) / 256, 256>>>();
    count_kernel<<<(E + 255) / 256, 256>>>(ei, E);
    scan_kernel<<<1, 1024>>>();
    fill_kernel<<<(E + 255) / 256, 256>>>(ei, E);
    xconv_kernel<<<(MTOT * (NF / 4) + 255) / 256, 256>>>(x);   // must precede agg
    wconv_kernel<<<(MO * KDIM + 511) / 512, 512>>>(Wl, Wr);
    agg_kernel<<<NN, 64>>>();
    dim3 ggrid((MTOT + BM - 1) / BM, MO / BN);
    mma_gemm_kernel<<<ggrid, 256>>>(bl, out);
}

// round 5
// speedup vs baseline: 3.1095x; 1.7043x over previous
#include <cuda_runtime.h>
#include <cuda_fp16.h>
#include <stdint.h>

// Problem constants (fixed shapes)
#define NB 2
#define NN 20000
#define NF 256
#define NE 640000
#define KDIM 512
#define MO 256
#define MTOT (NB*NN)        // 40000 GEMM rows
#define NDEG_PAD 20480      // padded for vector ops

// ---------------- device scratch ----------------
__device__ int   g_flag;
__device__ __align__(16) int g_deg[NDEG_PAD];
__device__ __align__(16) int g_off[NDEG_PAD];   // [NN+1] used; padded for STG.128
__device__ int   g_cursor[NN];
__device__ int   g_src[NE];
// A matrix [MTOT][512] fp16. cols 0..255 = agg, 256..511 = fp16 copy of x
__device__ __align__(16) __half g_A[(size_t)MTOT * KDIM];
// W concat [256][512] fp16: k<256 from W_l, else W_r
__device__ __align__(16) __half g_W[(size_t)MO * KDIM];

// ---------------- PTX helpers (base sm_103-safe only) ----------------
__device__ __forceinline__ uint32_t smem_u32(const void* p) {
    return (uint32_t)__cvta_generic_to_shared(p);
}
#define CP_ASYNC16(s, g) \
    asm volatile("cp.async.cg.shared.global [%0], [%1], 16;" :: "r"(s), "l"(g))
#define CP_COMMIT() asm volatile("cp.async.commit_group;" ::: "memory")
#define CP_WAIT0()  asm volatile("cp.async.wait_group 0;" ::: "memory")

__device__ __forceinline__ void ldmx4(uint32_t& r0, uint32_t& r1, uint32_t& r2, uint32_t& r3,
                                      uint32_t addr) {
    asm volatile("ldmatrix.sync.aligned.m8n8.x4.shared.b16 {%0,%1,%2,%3}, [%4];"
                 : "=r"(r0), "=r"(r1), "=r"(r2), "=r"(r3) : "r"(addr));
}
__device__ __forceinline__ void mma16816(float* c, const uint32_t* a, const uint32_t* b) {
    asm volatile(
        "mma.sync.aligned.m16n8k16.row.col.f32.f16.f16.f32 "
        "{%0,%1,%2,%3}, {%4,%5,%6,%7}, {%8,%9}, {%0,%1,%2,%3};"
        : "+f"(c[0]), "+f"(c[1]), "+f"(c[2]), "+f"(c[3])
        : "r"(a[0]), "r"(a[1]), "r"(a[2]), "r"(a[3]), "r"(b[0]), "r"(b[1]));
}

// ---------------- helpers ----------------
__device__ __forceinline__ int load_idx(const void* ei, long long pos) {
    if (g_flag) return (int)((const long long*)ei)[pos];
    return ((const int*)ei)[pos];
}

// ---------------- setup: detect dtype + zero counters ----------------
__global__ void zero_kernel(const void* ei) {
    int i = blockIdx.x * blockDim.x + threadIdx.x;
    if (i == 0) {
        const int2* p = (const int2*)ei;
        int is64 = 1;
        for (int q = 0; q < 64; q++)
            if (p[q].y != 0) { is64 = 0; break; }
        g_flag = is64;
    }
    if (i < NDEG_PAD) g_deg[i] = 0;
    if (i < NN) g_cursor[i] = 0;
}

__global__ void count_kernel(const void* __restrict__ ei, int E) {
    int e = blockIdx.x * blockDim.x + threadIdx.x;
    if (e < E) atomicAdd(&g_deg[load_idx(ei, (long long)E + e)], 1);
}

// single-block scan: 1024 threads x 20 elems, int4 loads AND int4 stores
__global__ void scan_kernel() {
    __shared__ int warp_sums[32];
    const int CH = 20;
    int t = threadIdx.x;
    int lane = t & 31, w = t >> 5;
    int v[CH];
    {
        int4 wv[5];
#pragma unroll
        for (int q = 0; q < 5; q++) wv[q] = ((const int4*)g_deg)[t * 5 + q];
        int s = 0;
#pragma unroll
        for (int q = 0; q < 5; q++) {
            s += wv[q].x; v[q * 4 + 0] = s;
            s += wv[q].y; v[q * 4 + 1] = s;
            s += wv[q].z; v[q * 4 + 2] = s;
            s += wv[q].w; v[q * 4 + 3] = s;
        }
    }
    int s = v[CH - 1];
    int x = s;
#pragma unroll
    for (int off = 1; off < 32; off *= 2) {
        int y = __shfl_up_sync(0xffffffffu, x, off);
        if (lane >= off) x += y;
    }
    if (lane == 31) warp_sums[w] = x;
    __syncthreads();
    if (w == 0) {
        int ws = warp_sums[lane];
#pragma unroll
        for (int off = 1; off < 32; off *= 2) {
            int y = __shfl_up_sync(0xffffffffu, ws, off);
            if (lane >= off) ws += y;
        }
        warp_sums[lane] = ws;
    }
    __syncthreads();
    int thrExcl = ((w > 0) ? warp_sums[w - 1] : 0) + (x - s);
    int arr[CH];
    arr[0] = thrExcl;
#pragma unroll
    for (int i = 1; i < CH; i++) arr[i] = thrExcl + v[i - 1];
#pragma unroll
    for (int q = 0; q < 5; q++)
        ((int4*)g_off)[t * 5 + q] = *(const int4*)&arr[q * 4];
}

__global__ void fill_kernel(const void* __restrict__ ei, int E) {
    int e = blockIdx.x * blockDim.x + threadIdx.x;
    if (e < E) {
        int t = load_idx(ei, (long long)E + e);
        int s = load_idx(ei, e);
        int pos = atomicAdd(&g_cursor[t], 1);
        g_src[g_off[t] + pos] = s;
    }
}

// ---------------- x -> fp16 A columns [256,512) ----------------
__global__ void xconv_kernel(const float* __restrict__ x) {
    int idx = blockIdx.x * blockDim.x + threadIdx.x;
    const int TOT = MTOT * (NF / 8);   // 8 floats per thread
    if (idx >= TOT) return;
    int m = idx >> 5;                  // 32 chunks of 8 per row
    int fq = (idx & 31) * 8;
    float4 v0 = ((const float4*)x)[idx * 2];
    float4 v1 = ((const float4*)x)[idx * 2 + 1];
    union { __half h[8]; uint4 u; } o;
    o.h[0] = __float2half_rn(v0.x); o.h[1] = __float2half_rn(v0.y);
    o.h[2] = __float2half_rn(v0.z); o.h[3] = __float2half_rn(v0.w);
    o.h[4] = __float2half_rn(v1.x); o.h[5] = __float2half_rn(v1.y);
    o.h[6] = __float2half_rn(v1.z); o.h[7] = __float2half_rn(v1.w);
    *(uint4*)&g_A[(size_t)m * KDIM + 256 + fq] = o.u;
}

// ---------------- W concat -> fp16 ----------------
__global__ void wconv_kernel(const float* __restrict__ Wl, const float* __restrict__ Wr) {
    int idx = blockIdx.x * blockDim.x + threadIdx.x;
    if (idx >= MO * KDIM / 2) return;  // 2 floats per thread
    int o = idx >> 8, k = (idx & 255) * 2;
    const float* src = (k < NF) ? (Wl + o * NF + k) : (Wr + o * NF + (k - NF));
    float2 v = *(const float2*)src;
    __half2 h = __floats2half2_rn(v.x, v.y);
    *(__half2*)&g_W[o * KDIM + k] = h;
}

// ---------------- mean aggregation: fp16 gather from g_A x-columns ----------------
__device__ __forceinline__ void acc8(float* acc, uint4 v) {
    const __half2* h = (const __half2*)&v;
#pragma unroll
    for (int q = 0; q < 4; q++) {
        float2 f = __half22float2(h[q]);
        acc[2 * q]     += f.x;
        acc[2 * q + 1] += f.y;
    }
}

__global__ __launch_bounds__(64)
void agg_kernel() {
    int node = blockIdx.x;
    int t = threadIdx.x;
    int batch = t >> 5, lane = t & 31;
    int s0 = g_off[node], s1 = g_off[node + 1];
    __shared__ int sSrc[64];
    const uint4* __restrict__ xb = (const uint4*)g_A;  // 64 uint4 per row
    size_t bbase = (size_t)batch * NN;
    float acc[8] = {0.f, 0.f, 0.f, 0.f, 0.f, 0.f, 0.f, 0.f};

    for (int base = s0; base < s1; base += 64) {
        int cnt = min(64, s1 - base);
        if (t < cnt) sSrc[t] = g_src[base + t];
        __syncthreads();
        int i = 0;
        for (; i + 4 <= cnt; i += 4) {
            uint4 v0 = xb[(bbase + sSrc[i + 0]) * 64 + 32 + lane];
            uint4 v1 = xb[(bbase + sSrc[i + 1]) * 64 + 32 + lane];
            uint4 v2 = xb[(bbase + sSrc[i + 2]) * 64 + 32 + lane];
            uint4 v3 = xb[(bbase + sSrc[i + 3]) * 64 + 32 + lane];
            acc8(acc, v0); acc8(acc, v1); acc8(acc, v2); acc8(acc, v3);
        }
        for (; i < cnt; i++) {
            uint4 v = xb[(bbase + sSrc[i]) * 64 + 32 + lane];
            acc8(acc, v);
        }
        __syncthreads();
    }

    float inv = 1.0f / fmaxf((float)(s1 - s0), 1.0f);
    union { __half h[8]; uint4 u; } hv;
#pragma unroll
    for (int j = 0; j < 8; j++) hv.h[j] = __float2half_rn(acc[j] * inv);
    *(uint4*)&g_A[(bbase + node) * (size_t)KDIM + lane * 8] = hv.u;
}

// ---------------- mma.sync GEMM (single fp16 pass, K=512) ----------------
#define BM 128
#define BN 128
#define BK 32
#define NIT 16
#define SKW 40   // halves per smem row (32 + 8 pad)

__global__ __launch_bounds__(256, 2)
void mma_gemm_kernel(const float* __restrict__ bl, float* __restrict__ out) {
    __shared__ __align__(16) __half As[2][BM * SKW];
    __shared__ __align__(16) __half Bs[2][BN * SKW];
    __shared__ float s_bias[BN];

    int tid = threadIdx.x;
    int lane = tid & 31, wid = tid >> 5;
    int bm = blockIdx.x * BM;
    int bn = blockIdx.y * BN;
    int wm = (wid & 3) * 32;     // warp tile 32x64
    int wn = (wid >> 2) * 64;

    if (tid < BN) s_bias[tid] = bl[bn + tid];

    uint32_t sA[2] = { smem_u32(&As[0][0]), smem_u32(&As[1][0]) };
    uint32_t sB[2] = { smem_u32(&Bs[0][0]), smem_u32(&Bs[1][0]) };

    float acc[2][8][4];
#pragma unroll
    for (int i = 0; i < 2; i++)
#pragma unroll
        for (int j = 0; j < 8; j++)
#pragma unroll
            for (int q = 0; q < 4; q++) acc[i][j][q] = 0.f;

    auto load_tiles = [&](int it, int buf) {
        int k0 = it << 5;
#pragma unroll
        for (int i = 0; i < 2; i++) {
            int c = tid + i * 256;       // 512 16B-chunks per tile
            int row = c >> 2, q = c & 3;
            int m = bm + row; if (m >= MTOT) m = MTOT - 1;
            CP_ASYNC16(sA[buf] + (row * SKW + q * 8) * 2,
                       g_A + (size_t)m * KDIM + k0 + q * 8);
            int n = bn + row;
            CP_ASYNC16(sB[buf] + (row * SKW + q * 8) * 2,
                       g_W + (size_t)n * KDIM + k0 + q * 8);
        }
        CP_COMMIT();
    };

    load_tiles(0, 0);
    int buf = 0;

    for (int it = 0; it < NIT; it++) {
        CP_WAIT0();
        __syncthreads();
        if (it + 1 < NIT) load_tiles(it + 1, buf ^ 1);

#pragma unroll
        for (int kk = 0; kk < 2; kk++) {
            uint32_t a[2][4], b[8][2];
#pragma unroll
            for (int mt = 0; mt < 2; mt++) {
                uint32_t addr = sA[buf] +
                    ((wm + mt * 16 + (lane & 15)) * SKW + kk * 16 + (lane >> 4) * 8) * 2;
                ldmx4(a[mt][0], a[mt][1], a[mt][2], a[mt][3], addr);
            }
#pragma unroll
            for (int np = 0; np < 4; np++) {
                int rowB = wn + np * 16 + (lane & 7) + ((lane >> 4) << 3);
                uint32_t addr = sB[buf] +
                    (rowB * SKW + kk * 16 + ((lane >> 3) & 1) * 8) * 2;
                ldmx4(b[2 * np][0], b[2 * np][1], b[2 * np + 1][0], b[2 * np + 1][1], addr);
            }
#pragma unroll
            for (int mt = 0; mt < 2; mt++)
#pragma unroll
                for (int nt = 0; nt < 8; nt++)
                    mma16816(acc[mt][nt], a[mt], b[nt]);
        }
        __syncthreads();
        buf ^= 1;
    }

    // epilogue: bias + relu, float2 stores
    int g = lane >> 2, t4 = lane & 3;
#pragma unroll
    for (int mt = 0; mt < 2; mt++) {
#pragma unroll
        for (int nt = 0; nt < 8; nt++) {
            int o = bn + wn + nt * 8 + t4 * 2;
            float b0 = s_bias[wn + nt * 8 + t4 * 2];
            float b1 = s_bias[wn + nt * 8 + t4 * 2 + 1];
            int m0 = bm + wm + mt * 16 + g;
            if (m0 < MTOT) {
                float2 v;
                v.x = fmaxf(acc[mt][nt][0] + b0, 0.f);
                v.y = fmaxf(acc[mt][nt][1] + b1, 0.f);
                *(float2*)(out + (size_t)m0 * MO + o) = v;
            }
            int m1 = m0 + 8;
            if (m1 < MTOT) {
                float2 v;
                v.x = fmaxf(acc[mt][nt][2] + b0, 0.f);
                v.y = fmaxf(acc[mt][nt][3] + b1, 0.f);
                *(float2*)(out + (size_t)m1 * MO + o) = v;
            }
        }
    }
}

// ---------------- launch ----------------
extern "C" void kernel_launch(void* const* d_in, const int* in_sizes, int n_in,
                              void* d_out, int out_size) {
    const float* x  = (const float*)d_in[0];
    const void*  ei = d_in[1];
    const float* Wl = (const float*)d_in[2];
    const float* bl = (const float*)d_in[3];
    const float* Wr = (const float*)d_in[4];
    float* out = (float*)d_out;
    int E = in_sizes[1] / 2;

    zero_kernel<<<(NDEG_PAD + 255) / 256, 256>>>(ei);
    count_kernel<<<(E + 255) / 256, 256>>>(ei, E);
    scan_kernel<<<1, 1024>>>();
    fill_kernel<<<(E + 255) / 256, 256>>>(ei, E);
    xconv_kernel<<<(MTOT * (NF / 8) + 255) / 256, 256>>>(x);   // must precede agg
    wconv_kernel<<<(MO * KDIM / 2 + 255) / 256, 256>>>(Wl, Wr);
    agg_kernel<<<NN, 64>>>();
    dim3 ggrid((MTOT + BM - 1) / BM, MO / BN);
    mma_gemm_kernel<<<ggrid, 256>>>(bl, out);
}